// round 12
// baseline (speedup 1.0000x reference)
#include <cuda_runtime.h>
#include <cuda_bf16.h>
#include <cstdint>

#define BB 8
#define TT 512
#define DD 1024
#define HH 16
#define DH 64

// bf16 hi/lo splits (device globals; no allocs allowed)
__device__ unsigned short g_Qh[BB * HH * TT * DH];   // [bh][t][d]  (Q pre-scaled by 1/8)
__device__ unsigned short g_Ql[BB * HH * TT * DH];
__device__ unsigned short g_Kh[BB * HH * TT * DH];   // [bh][t][d]
__device__ unsigned short g_Kl[BB * HH * TT * DH];
__device__ unsigned short g_Vh[BB * HH * DH * TT];   // [bh][d][t]
__device__ unsigned short g_Vl[BB * HH * DH * TT];
__device__ unsigned short g_Ah[BB * TT * DD];        // attention out split [m][k]
__device__ unsigned short g_Al[BB * TT * DD];
__device__ unsigned short g_Wh[DD * DD];             // W^T: [n][k]
__device__ unsigned short g_Wl[DD * DD];

__device__ __forceinline__ void mma16816(float* c, const uint32_t* a, const uint32_t* b) {
    asm volatile(
        "mma.sync.aligned.m16n8k16.row.col.f32.bf16.bf16.f32 "
        "{%0,%1,%2,%3}, {%4,%5,%6,%7}, {%8,%9}, {%0,%1,%2,%3};"
        : "+f"(c[0]), "+f"(c[1]), "+f"(c[2]), "+f"(c[3])
        : "r"(a[0]), "r"(a[1]), "r"(a[2]), "r"(a[3]), "r"(b[0]), "r"(b[1]));
}

__device__ __forceinline__ void ldm_x4(uint32_t* r, uint32_t saddr) {
    asm volatile("ldmatrix.sync.aligned.m8n8.x4.shared.b16 {%0,%1,%2,%3}, [%4];"
        : "=r"(r[0]), "=r"(r[1]), "=r"(r[2]), "=r"(r[3]) : "r"(saddr));
}

__device__ __forceinline__ void fsplit(float v, unsigned short& h, unsigned short& l) {
    uint32_t b = __float_as_uint(v);
    h = (unsigned short)(b >> 16);
    float lo = v - __uint_as_float(b & 0xFFFF0000u);
    uint32_t p;
    asm("cvt.rn.bf16x2.f32 %0, %1, %2;" : "=r"(p) : "f"(lo), "f"(lo));
    l = (unsigned short)(p & 0xFFFF);
}

__device__ __forceinline__ void cp16(unsigned short* sdst, const unsigned short* gsrc) {
    uint32_t s = (uint32_t)__cvta_generic_to_shared(sdst);
    asm volatile("cp.async.cg.shared.global [%0], [%1], 16;" :: "r"(s), "l"(gsrc));
}
__device__ __forceinline__ void cp16g(void* sdst, const void* gsrc) {
    uint32_t s = (uint32_t)__cvta_generic_to_shared(sdst);
    asm volatile("cp.async.cg.shared.global [%0], [%1], 16;" :: "r"(s), "l"(gsrc));
}
#define CP_COMMIT() asm volatile("cp.async.commit_group;" ::: "memory")
#define CP_WAIT1()  asm volatile("cp.async.wait_group 1;" ::: "memory")
#define CP_WAIT0()  asm volatile("cp.async.wait_group 0;" ::: "memory")

// ---------------------------------------------------------------------------
// Kernel 1: QKV projections, single-pass, weights via cp.async.
// grid (T/64, B*H), 256 threads.  (unchanged from R11)
// ---------------------------------------------------------------------------
#define QKV_XS   0
#define QKV_W3   (64 * 65)
#define QKV_SMEM ((QKV_W3 + 3 * 64 * 64) * 4)

__global__ __launch_bounds__(256) void qkv_kernel(
    const float* __restrict__ X,
    const float* __restrict__ Wq, const float* __restrict__ bq,
    const float* __restrict__ Wk, const float* __restrict__ bk,
    const float* __restrict__ Wv, const float* __restrict__ bv)
{
    extern __shared__ float qsm[];
    float* Xs = qsm + QKV_XS;
    float* W3 = qsm + QKV_W3;

    int bh = blockIdx.y;
    int b  = bh >> 4;
    int h  = bh & 15;
    int t0 = blockIdx.x * 64;
    int tid = threadIdx.x;
    int tn = tid & 15;
    int tm = tid >> 4;

    {
        const float* Wsrc[3] = {Wq + h * DH * DH, Wk + h * DH * DH, Wv + h * DH * DH};
        #pragma unroll
        for (int p = 0; p < 3; p++)
            for (int i = tid; i < 1024; i += 256)
                cp16g(&W3[p * 4096 + i * 4], Wsrc[p] + i * 4);
        CP_COMMIT();
    }

    const float* Xb = X + ((size_t)(b * TT + t0)) * DD + h * DH;
    for (int i = tid; i < 1024; i += 256) {
        int t = i >> 4, d4 = (i & 15) * 4;
        float4 v = *reinterpret_cast<const float4*>(Xb + (size_t)t * DD + d4);
        Xs[(d4 + 0) * 65 + t] = v.x;
        Xs[(d4 + 1) * 65 + t] = v.y;
        Xs[(d4 + 2) * 65 + t] = v.z;
        Xs[(d4 + 3) * 65 + t] = v.w;
    }
    CP_WAIT0();
    __syncthreads();

    float acc[3][4][4];
    #pragma unroll
    for (int p = 0; p < 3; p++)
        #pragma unroll
        for (int j = 0; j < 4; j++)
            #pragma unroll
            for (int i = 0; i < 4; i++) acc[p][j][i] = 0.0f;

    #pragma unroll 4
    for (int d = 0; d < 64; d++) {
        float bb[4];
        #pragma unroll
        for (int i = 0; i < 4; i++) bb[i] = Xs[d * 65 + tn + 16 * i];
        #pragma unroll
        for (int p = 0; p < 3; p++) {
            float a[4];
            #pragma unroll
            for (int j = 0; j < 4; j++) a[j] = W3[p * 4096 + d * 64 + tm * 4 + j];
            #pragma unroll
            for (int j = 0; j < 4; j++)
                #pragma unroll
                for (int i = 0; i < 4; i++)
                    acc[p][j][i] += a[j] * bb[i];
        }
    }
    __syncthreads();

    unsigned short* stg = reinterpret_cast<unsigned short*>(W3);
    const float* bl[3] = {bq, bk, bv};
    #pragma unroll
    for (int p = 0; p < 3; p++) {
        unsigned short* sH = stg + p * 8192;
        unsigned short* sL = sH + 4096;
        float qscale = (p == 0) ? 0.125f : 1.0f;
        #pragma unroll
        for (int j = 0; j < 4; j++) {
            int e = tm * 4 + j;
            float be = bl[p][h * DH + e];
            #pragma unroll
            for (int i = 0; i < 4; i++) {
                int t = tn + 16 * i;
                float v = (acc[p][j][i] + be) * qscale;
                unsigned short hh, ll;
                fsplit(v, hh, ll);
                int idx = (p < 2) ? (t * 64 + e) : (e * 64 + t);
                sH[idx] = hh;
                sL[idx] = ll;
            }
        }
    }
    __syncthreads();

    #pragma unroll
    for (int p = 0; p < 3; p++) {
        unsigned short* sH = stg + p * 8192;
        unsigned short* sL = sH + 4096;
        unsigned short *Hd, *Ld;
        if (p == 0)      { Hd = g_Qh; Ld = g_Ql; }
        else if (p == 1) { Hd = g_Kh; Ld = g_Kl; }
        else             { Hd = g_Vh; Ld = g_Vl; }
        for (int i = tid; i < 512; i += 256) {
            int row = i >> 3, c8 = (i & 7) * 8;
            uint4 vh = reinterpret_cast<const uint4*>(sH)[i];
            uint4 vl = reinterpret_cast<const uint4*>(sL)[i];
            size_t off;
            if (p < 2) off = ((size_t)bh * TT + t0 + row) * DH + c8;
            else       off = ((size_t)bh * DH + row) * TT + t0 + c8;
            *reinterpret_cast<uint4*>(Hd + off) = vh;
            *reinterpret_cast<uint4*>(Ld + off) = vl;
        }
    }
}

// ---------------------------------------------------------------------------
// Kernel 2: flash attention, Q fragments REGISTER-HOISTED (loop-invariant),
// Q smem reused as KV stage 1. 256 threads (8 warps, 16q each).
// ---------------------------------------------------------------------------
#define ASTR 72
#define AKV_STG (4 * 64 * ASTR)            // 18432 ushorts per stage
#define A_QSTG  AKV_STG                    // Q staging overlaps stage 1
#define A_MSK   (2 * AKV_STG)              // 36864
#define ATTN_SMEM ((A_MSK + 1024) * 2)     // 75776 bytes

__global__ __launch_bounds__(256) void attn_mma_kernel(const int* __restrict__ mask)
{
    extern __shared__ unsigned short shm[];
    int* sMask = (int*)(shm + A_MSK);
    uint32_t sb = (uint32_t)__cvta_generic_to_shared(shm);

    int tid = threadIdx.x;
    int wid = tid >> 5;
    int lane = tid & 31;
    int g = lane >> 2;
    int t = lane & 3;
    int wq = wid * 16;

    int bh = blockIdx.y;
    int b  = bh >> 4;
    int h  = bh & 15;
    int q0 = blockIdx.x * 128;

    int aRow  = (lane & 15);
    int aCol8 = (lane >> 4) * 8;
    int bRow  = ((lane >> 4) & 1) * 8 + (lane & 7);
    int bCol8 = ((lane >> 3) & 1) * 8;

    auto load_kv = [&](int stage, int kb) {
        unsigned short* stg = shm + stage * AKV_STG;
        for (int i = tid; i < 512; i += 256) {
            int row = i >> 3, c8 = (i & 7) * 8;
            size_t ko = ((size_t)bh * TT + kb + row) * DH + c8;
            size_t vo = ((size_t)bh * DH + row) * TT + kb + c8;
            cp16(stg + row * ASTR + c8,         g_Kh + ko);
            cp16(stg + 4608 + row * ASTR + c8,  g_Kl + ko);
            cp16(stg + 9216 + row * ASTR + c8,  g_Vh + vo);
            cp16(stg + 13824 + row * ASTR + c8, g_Vl + vo);
        }
    };

    // stage-0 KV prefetch first (cp.async), then Q staging + mask (regular)
    load_kv(0, 0);
    CP_COMMIT();
    {
        const unsigned short* Qhg = g_Qh + ((size_t)bh * TT + q0) * DH;
        const unsigned short* Qlg = g_Ql + ((size_t)bh * TT + q0) * DH;
        for (int i = tid; i < 1024; i += 256) {
            int row = i >> 3, c8 = (i & 7) * 8;
            *reinterpret_cast<uint4*>(&shm[A_QSTG + row * ASTR + c8]) =
                *reinterpret_cast<const uint4*>(Qhg + row * DH + c8);
            *reinterpret_cast<uint4*>(&shm[A_QSTG + 9216 + row * ASTR + c8]) =
                *reinterpret_cast<const uint4*>(Qlg + row * DH + c8);
        }
        for (int i = tid; i < TT; i += 256) sMask[i] = mask[b * TT + i];
    }
    __syncthreads();

    // hoist ALL Q fragments into registers (loop-invariant)
    uint32_t qh[4][4], ql[4][4];
    {
        uint32_t qBase = sb + 2 * (A_QSTG + (wq + aRow) * ASTR + aCol8);
        #pragma unroll
        for (int ks = 0; ks < 4; ks++) {
            ldm_x4(qh[ks], qBase + 32 * ks);
            ldm_x4(ql[ks], qBase + 32 * ks + 2 * 9216);
        }
    }
    __syncthreads();   // all warps done reading Q staging (== KV stage 1)

    float O[8][4];
    float m_[2], l_[2];
    m_[0] = m_[1] = -1e30f;
    l_[0] = l_[1] = 0.0f;
    #pragma unroll
    for (int nt = 0; nt < 8; nt++)
        #pragma unroll
        for (int r = 0; r < 4; r++) O[nt][r] = 0.0f;

    for (int kt = 0; kt < 8; kt++) {
        int kb = kt * 64;
        CP_WAIT0();          // stage kt resident
        __syncthreads();     // all warps done reading the buffer being overwritten

        if (kt + 1 < 8) {
            load_kv((kt + 1) & 1, kb + 64);
            CP_COMMIT();
        }

        uint32_t stgOff = 2 * ((kt & 1) * AKV_STG);
        uint32_t kBase = sb + stgOff + 2 * (bRow * ASTR + bCol8);
        uint32_t vBase = kBase + 2 * 9216;

        float S[8][4];
        #pragma unroll
        for (int nt = 0; nt < 8; nt++)
            #pragma unroll
            for (int r = 0; r < 4; r++) S[nt][r] = 0.0f;

        #pragma unroll
        for (int ks = 0; ks < 4; ks++) {
            uint32_t kh[16], kl[16];
            #pragma unroll
            for (int p = 0; p < 4; p++) {
                ldm_x4(&kh[4 * p], kBase + 2 * (p * 16 * ASTR + ks * 16));
                ldm_x4(&kl[4 * p], kBase + 2 * (p * 16 * ASTR + ks * 16 + 4608));
            }
            #pragma unroll
            for (int nt = 0; nt < 8; nt++) {
                mma16816(S[nt], qh[ks], &kh[2 * nt]);
                mma16816(S[nt], qh[ks], &kl[2 * nt]);
                mma16816(S[nt], ql[ks], &kh[2 * nt]);
            }
        }

        #pragma unroll
        for (int nt = 0; nt < 8; nt++) {
            int mk0 = sMask[kb + nt * 8 + 2 * t];
            int mk1 = sMask[kb + nt * 8 + 2 * t + 1];
            if (mk0 <= 0) { S[nt][0] = -1e9f; S[nt][2] = -1e9f; }
            if (mk1 <= 0) { S[nt][1] = -1e9f; S[nt][3] = -1e9f; }
        }
        #pragma unroll
        for (int r = 0; r < 2; r++) {
            float mx = -1e30f;
            #pragma unroll
            for (int nt = 0; nt < 8; nt++) {
                mx = fmaxf(mx, S[nt][2 * r]);
                mx = fmaxf(mx, S[nt][2 * r + 1]);
            }
            mx = fmaxf(mx, __shfl_xor_sync(0xffffffffu, mx, 1));
            mx = fmaxf(mx, __shfl_xor_sync(0xffffffffu, mx, 2));
            float mnew  = fmaxf(m_[r], mx);
            float alpha = __expf(m_[r] - mnew);
            float rs = 0.0f;
            #pragma unroll
            for (int nt = 0; nt < 8; nt++) {
                float e0 = __expf(S[nt][2 * r]     - mnew);
                float e1 = __expf(S[nt][2 * r + 1] - mnew);
                S[nt][2 * r]     = e0;
                S[nt][2 * r + 1] = e1;
                rs += e0 + e1;
            }
            rs += __shfl_xor_sync(0xffffffffu, rs, 1);
            rs += __shfl_xor_sync(0xffffffffu, rs, 2);
            l_[r] = l_[r] * alpha + rs;
            m_[r] = mnew;
            #pragma unroll
            for (int nt = 0; nt < 8; nt++) {
                O[nt][2 * r]     *= alpha;
                O[nt][2 * r + 1] *= alpha;
            }
        }

        #pragma unroll
        for (int ks = 0; ks < 4; ks++) {
            uint32_t ph[4], pl[4];
            #pragma unroll
            for (int half = 0; half < 2; half++) {
                const float* sv = S[2 * ks + half];
                uint32_t b0 = __float_as_uint(sv[0]);
                uint32_t b1 = __float_as_uint(sv[1]);
                uint32_t b2 = __float_as_uint(sv[2]);
                uint32_t b3 = __float_as_uint(sv[3]);
                ph[2 * half]     = __byte_perm(b0, b1, 0x7632);
                ph[2 * half + 1] = __byte_perm(b2, b3, 0x7632);
                float l0 = sv[0] - __uint_as_float(b0 & 0xFFFF0000u);
                float l1 = sv[1] - __uint_as_float(b1 & 0xFFFF0000u);
                float l2 = sv[2] - __uint_as_float(b2 & 0xFFFF0000u);
                float l3 = sv[3] - __uint_as_float(b3 & 0xFFFF0000u);
                asm("cvt.rn.bf16x2.f32 %0, %1, %2;"
                    : "=r"(pl[2 * half]) : "f"(l1), "f"(l0));
                asm("cvt.rn.bf16x2.f32 %0, %1, %2;"
                    : "=r"(pl[2 * half + 1]) : "f"(l3), "f"(l2));
            }
            uint32_t vh[16], vl[16];
            #pragma unroll
            for (int p = 0; p < 4; p++) {
                ldm_x4(&vh[4 * p], vBase + 2 * (p * 16 * ASTR + ks * 16));
                ldm_x4(&vl[4 * p], vBase + 2 * (p * 16 * ASTR + ks * 16 + 4608));
            }
            #pragma unroll
            for (int nt = 0; nt < 8; nt++) {
                mma16816(O[nt], ph, &vh[2 * nt]);
                mma16816(O[nt], ph, &vl[2 * nt]);
                mma16816(O[nt], pl, &vh[2 * nt]);
            }
        }
    }

    #pragma unroll
    for (int r = 0; r < 2; r++) {
        float inv = 1.0f / l_[r];
        int mrow = b * TT + q0 + wq + g + 8 * r;
        size_t base = (size_t)mrow * DD + h * DH;
        #pragma unroll
        for (int nt = 0; nt < 8; nt++) {
            float v0 = O[nt][2 * r]     * inv;
            float v1 = O[nt][2 * r + 1] * inv;
            uint32_t b0 = __float_as_uint(v0), b1 = __float_as_uint(v1);
            uint32_t hp = __byte_perm(b0, b1, 0x7632);
            float l0 = v0 - __uint_as_float(b0 & 0xFFFF0000u);
            float l1 = v1 - __uint_as_float(b1 & 0xFFFF0000u);
            uint32_t lp;
            asm("cvt.rn.bf16x2.f32 %0, %1, %2;" : "=r"(lp) : "f"(l1), "f"(l0));
            *reinterpret_cast<uint32_t*>(g_Ah + base + nt * 8 + 2 * t) = hp;
            *reinterpret_cast<uint32_t*>(g_Al + base + nt * 8 + 2 * t) = lp;
        }
    }
}

// ---------------------------------------------------------------------------
// Kernel 3: Wf [k][n] fp32 -> g_Wh/g_Wl [n][k] bf16 (transpose + split)
// ---------------------------------------------------------------------------
__global__ __launch_bounds__(256) void convW_kernel(const float* __restrict__ Wf)
{
    __shared__ float t[32][33];
    int k0 = blockIdx.x * 32, n0 = blockIdx.y * 32;
    int tx = threadIdx.x & 31, ty = threadIdx.x >> 5;
    #pragma unroll
    for (int j = 0; j < 4; j++)
        t[ty + 8 * j][tx] = Wf[(size_t)(k0 + ty + 8 * j) * DD + n0 + tx];
    __syncthreads();
    #pragma unroll
    for (int j = 0; j < 4; j++) {
        int k = k0 + tx, n = n0 + ty + 8 * j;
        float v = t[tx][ty + 8 * j];
        unsigned short hh, ll;
        fsplit(v, hh, ll);
        g_Wh[(size_t)n * DD + k] = hh;
        g_Wl[(size_t)n * DD + k] = ll;
    }
}

// ---------------------------------------------------------------------------
// Kernel 4: fusion GEMM. R8 geometry AND R8 ordering (compute, then prefetch).
// CTA 128m x 64n, 8 warps 4m x 2n, BK=32, 3-stage cp.async, 2 CTAs/SM.
// ---------------------------------------------------------------------------
#define F2 40
#define FST_A  (128 * F2)
#define FST_B  (64 * F2)
#define FST_SZ (2 * FST_A + 2 * FST_B)
#define FNST 3
#define FUSE_SMEM (FNST * FST_SZ * 2)

__global__ __launch_bounds__(256, 2) void fuse_mma_kernel(
    const float* __restrict__ bf, float* __restrict__ C)
{
    extern __shared__ unsigned short fsm[];
    uint32_t sb = (uint32_t)__cvta_generic_to_shared(fsm);

    int tid = threadIdx.x;
    int wid = tid >> 5;
    int lane = tid & 31;
    int g = lane >> 2;
    int t = lane & 3;
    int wm = wid >> 1;
    int wn = wid & 1;

    int n0 = blockIdx.x * 64;
    int m0 = blockIdx.y * 128;

    int aRow  = (lane & 15);
    int aCol8 = (lane >> 4) * 8;
    int bRow  = ((lane >> 4) & 1) * 8 + (lane & 7);
    int bCol8 = ((lane >> 3) & 1) * 8;

    auto load_stage = [&](int stage, int k0) {
        unsigned short* st = fsm + stage * FST_SZ;
        for (int i = tid; i < 512; i += 256) {
            int row = i >> 2, c = (i & 3) * 8;
            size_t ga = (size_t)(m0 + row) * DD + k0 + c;
            cp16(st + row * F2 + c,          g_Ah + ga);
            cp16(st + FST_A + row * F2 + c,  g_Al + ga);
        }
        {
            int i = tid & 255;
            int row = i >> 2, c = (i & 3) * 8;
            size_t gb = (size_t)(n0 + row) * DD + k0 + c;
            cp16(st + 2 * FST_A + row * F2 + c,          g_Wh + gb);
            cp16(st + 2 * FST_A + FST_B + row * F2 + c,  g_Wl + gb);
        }
    };

    float acc[2][4][4];
    #pragma unroll
    for (int mt = 0; mt < 2; mt++)
        #pragma unroll
        for (int nt = 0; nt < 4; nt++)
            #pragma unroll
            for (int r = 0; r < 4; r++) acc[mt][nt][r] = 0.0f;

    load_stage(0, 0);
    CP_COMMIT();
    load_stage(1, 32);
    CP_COMMIT();

    uint32_t aBaseRow = 2 * ((wm * 32 + aRow) * F2 + aCol8);
    uint32_t bBaseRow = 2 * ((wn * 32 + bRow) * F2 + bCol8);

    for (int kt = 0; kt < 32; kt++) {
        CP_WAIT1();
        __syncthreads();

        uint32_t stOff = sb + (uint32_t)((kt % 3) * FST_SZ) * 2;

        #pragma unroll
        for (int ks = 0; ks < 2; ks++) {
            int k = ks * 16;
            uint32_t ah[2][4], al[2][4];
            #pragma unroll
            for (int mt = 0; mt < 2; mt++) {
                uint32_t ua = stOff + aBaseRow + 2 * (mt * 16 * F2 + k);
                ldm_x4(ah[mt], ua);
                ldm_x4(al[mt], ua + 2 * FST_A);
            }
            uint32_t bh[8], blo[8];
            #pragma unroll
            for (int p = 0; p < 2; p++) {
                uint32_t ub = stOff + bBaseRow + 2 * (2 * FST_A + p * 16 * F2 + k);
                ldm_x4(&bh[4 * p], ub);
                ldm_x4(&blo[4 * p], ub + 2 * FST_B);
            }
            #pragma unroll
            for (int mt = 0; mt < 2; mt++)
                #pragma unroll
                for (int nt = 0; nt < 4; nt++) {
                    mma16816(acc[mt][nt], ah[mt], &bh[2 * nt]);
                    mma16816(acc[mt][nt], ah[mt], &blo[2 * nt]);
                    mma16816(acc[mt][nt], al[mt], &bh[2 * nt]);
                }
        }
        __syncthreads();

        if (kt + 2 < 32) load_stage((kt + 2) % 3, (kt + 2) * 32);
        CP_COMMIT();
    }

    #pragma unroll
    for (int nt = 0; nt < 4; nt++) {
        int n = n0 + wn * 32 + nt * 8 + t * 2;
        float b0 = bf[n], b1 = bf[n + 1];
        #pragma unroll
        for (int mt = 0; mt < 2; mt++) {
            int m = m0 + wm * 32 + mt * 16 + g;
            float2 v0 = make_float2(acc[mt][nt][0] + b0, acc[mt][nt][1] + b1);
            float2 v1 = make_float2(acc[mt][nt][2] + b0, acc[mt][nt][3] + b1);
            *reinterpret_cast<float2*>(C + (size_t)m * DD + n) = v0;
            *reinterpret_cast<float2*>(C + (size_t)(m + 8) * DD + n) = v1;
        }
    }
}

// ---------------------------------------------------------------------------
extern "C" void kernel_launch(void* const* d_in, const int* in_sizes, int n_in,
                              void* d_out, int out_size)
{
    const float* X    = (const float*)d_in[0];
    const int*   mask = (const int*)  d_in[1];
    const float* Wq   = (const float*)d_in[2];
    const float* bq   = (const float*)d_in[3];
    const float* Wk   = (const float*)d_in[4];
    const float* bk   = (const float*)d_in[5];
    const float* Wv   = (const float*)d_in[6];
    const float* bv   = (const float*)d_in[7];
    const float* Wf   = (const float*)d_in[8];
    const float* bf   = (const float*)d_in[9];
    float* out = (float*)d_out;

    cudaFuncSetAttribute(qkv_kernel,
                         cudaFuncAttributeMaxDynamicSharedMemorySize, QKV_SMEM);
    cudaFuncSetAttribute(attn_mma_kernel,
                         cudaFuncAttributeMaxDynamicSharedMemorySize, ATTN_SMEM);
    cudaFuncSetAttribute(fuse_mma_kernel,
                         cudaFuncAttributeMaxDynamicSharedMemorySize, FUSE_SMEM);

    dim3 grid1(TT / 64, BB * HH);
    qkv_kernel<<<grid1, 256, QKV_SMEM>>>(X, Wq, bq, Wk, bk, Wv, bv);

    convW_kernel<<<dim3(32, 32), 256>>>(Wf);

    dim3 grid2(TT / 128, BB * HH);
    attn_mma_kernel<<<grid2, 256, ATTN_SMEM>>>(mask);

    dim3 grid4(DD / 64, (BB * TT) / 128);
    fuse_mma_kernel<<<grid4, 256, FUSE_SMEM>>>(bf, out);
}

// round 13
// speedup vs baseline: 1.0729x; 1.0729x over previous
#include <cuda_runtime.h>
#include <cuda_bf16.h>
#include <cstdint>

#define BB 8
#define TT 512
#define DD 1024
#define HH 16
#define DH 64

// bf16 hi/lo splits (device globals; no allocs allowed)
__device__ unsigned short g_Qh[BB * HH * TT * DH];   // [bh][t][d]  (Q pre-scaled by 1/8)
__device__ unsigned short g_Ql[BB * HH * TT * DH];
__device__ unsigned short g_Kh[BB * HH * TT * DH];   // [bh][t][d]
__device__ unsigned short g_Kl[BB * HH * TT * DH];
__device__ unsigned short g_Vh[BB * HH * DH * TT];   // [bh][d][t]
__device__ unsigned short g_Vl[BB * HH * DH * TT];
__device__ unsigned short g_Ah[BB * TT * DD];        // attention out split [m][k]
__device__ unsigned short g_Al[BB * TT * DD];
__device__ unsigned short g_Wh[DD * DD];             // W^T: [n][k]
__device__ unsigned short g_Wl[DD * DD];

__device__ __forceinline__ void mma16816(float* c, const uint32_t* a, const uint32_t* b) {
    asm volatile(
        "mma.sync.aligned.m16n8k16.row.col.f32.bf16.bf16.f32 "
        "{%0,%1,%2,%3}, {%4,%5,%6,%7}, {%8,%9}, {%0,%1,%2,%3};"
        : "+f"(c[0]), "+f"(c[1]), "+f"(c[2]), "+f"(c[3])
        : "r"(a[0]), "r"(a[1]), "r"(a[2]), "r"(a[3]), "r"(b[0]), "r"(b[1]));
}

__device__ __forceinline__ void ldm_x4(uint32_t* r, uint32_t saddr) {
    asm volatile("ldmatrix.sync.aligned.m8n8.x4.shared.b16 {%0,%1,%2,%3}, [%4];"
        : "=r"(r[0]), "=r"(r[1]), "=r"(r[2]), "=r"(r[3]) : "r"(saddr));
}

__device__ __forceinline__ void fsplit(float v, unsigned short& h, unsigned short& l) {
    uint32_t b = __float_as_uint(v);
    h = (unsigned short)(b >> 16);
    float lo = v - __uint_as_float(b & 0xFFFF0000u);
    uint32_t p;
    asm("cvt.rn.bf16x2.f32 %0, %1, %2;" : "=r"(p) : "f"(lo), "f"(lo));
    l = (unsigned short)(p & 0xFFFF);
}

__device__ __forceinline__ void cp16(unsigned short* sdst, const unsigned short* gsrc) {
    uint32_t s = (uint32_t)__cvta_generic_to_shared(sdst);
    asm volatile("cp.async.cg.shared.global [%0], [%1], 16;" :: "r"(s), "l"(gsrc));
}
__device__ __forceinline__ void cp16g(void* sdst, const void* gsrc) {
    uint32_t s = (uint32_t)__cvta_generic_to_shared(sdst);
    asm volatile("cp.async.cg.shared.global [%0], [%1], 16;" :: "r"(s), "l"(gsrc));
}
#define CP_COMMIT() asm volatile("cp.async.commit_group;" ::: "memory")
#define CP_WAIT1()  asm volatile("cp.async.wait_group 1;" ::: "memory")
#define CP_WAIT0()  asm volatile("cp.async.wait_group 0;" ::: "memory")

// ---------------------------------------------------------------------------
// Kernel 1: QKV projections, single-pass, weights via cp.async.
// grid (T/64, B*H), 256 threads.
// ---------------------------------------------------------------------------
#define QKV_XS   0
#define QKV_W3   (64 * 65)
#define QKV_SMEM ((QKV_W3 + 3 * 64 * 64) * 4)

__global__ __launch_bounds__(256) void qkv_kernel(
    const float* __restrict__ X,
    const float* __restrict__ Wq, const float* __restrict__ bq,
    const float* __restrict__ Wk, const float* __restrict__ bk,
    const float* __restrict__ Wv, const float* __restrict__ bv)
{
    extern __shared__ float qsm[];
    float* Xs = qsm + QKV_XS;
    float* W3 = qsm + QKV_W3;

    int bh = blockIdx.y;
    int b  = bh >> 4;
    int h  = bh & 15;
    int t0 = blockIdx.x * 64;
    int tid = threadIdx.x;
    int tn = tid & 15;
    int tm = tid >> 4;

    {
        const float* Wsrc[3] = {Wq + h * DH * DH, Wk + h * DH * DH, Wv + h * DH * DH};
        #pragma unroll
        for (int p = 0; p < 3; p++)
            for (int i = tid; i < 1024; i += 256)
                cp16g(&W3[p * 4096 + i * 4], Wsrc[p] + i * 4);
        CP_COMMIT();
    }

    const float* Xb = X + ((size_t)(b * TT + t0)) * DD + h * DH;
    for (int i = tid; i < 1024; i += 256) {
        int t = i >> 4, d4 = (i & 15) * 4;
        float4 v = *reinterpret_cast<const float4*>(Xb + (size_t)t * DD + d4);
        Xs[(d4 + 0) * 65 + t] = v.x;
        Xs[(d4 + 1) * 65 + t] = v.y;
        Xs[(d4 + 2) * 65 + t] = v.z;
        Xs[(d4 + 3) * 65 + t] = v.w;
    }
    CP_WAIT0();
    __syncthreads();

    float acc[3][4][4];
    #pragma unroll
    for (int p = 0; p < 3; p++)
        #pragma unroll
        for (int j = 0; j < 4; j++)
            #pragma unroll
            for (int i = 0; i < 4; i++) acc[p][j][i] = 0.0f;

    #pragma unroll 4
    for (int d = 0; d < 64; d++) {
        float bb[4];
        #pragma unroll
        for (int i = 0; i < 4; i++) bb[i] = Xs[d * 65 + tn + 16 * i];
        #pragma unroll
        for (int p = 0; p < 3; p++) {
            float a[4];
            #pragma unroll
            for (int j = 0; j < 4; j++) a[j] = W3[p * 4096 + d * 64 + tm * 4 + j];
            #pragma unroll
            for (int j = 0; j < 4; j++)
                #pragma unroll
                for (int i = 0; i < 4; i++)
                    acc[p][j][i] += a[j] * bb[i];
        }
    }
    __syncthreads();

    unsigned short* stg = reinterpret_cast<unsigned short*>(W3);
    const float* bl[3] = {bq, bk, bv};
    #pragma unroll
    for (int p = 0; p < 3; p++) {
        unsigned short* sH = stg + p * 8192;
        unsigned short* sL = sH + 4096;
        float qscale = (p == 0) ? 0.125f : 1.0f;
        #pragma unroll
        for (int j = 0; j < 4; j++) {
            int e = tm * 4 + j;
            float be = bl[p][h * DH + e];
            #pragma unroll
            for (int i = 0; i < 4; i++) {
                int t = tn + 16 * i;
                float v = (acc[p][j][i] + be) * qscale;
                unsigned short hh, ll;
                fsplit(v, hh, ll);
                int idx = (p < 2) ? (t * 64 + e) : (e * 64 + t);
                sH[idx] = hh;
                sL[idx] = ll;
            }
        }
    }
    __syncthreads();

    #pragma unroll
    for (int p = 0; p < 3; p++) {
        unsigned short* sH = stg + p * 8192;
        unsigned short* sL = sH + 4096;
        unsigned short *Hd, *Ld;
        if (p == 0)      { Hd = g_Qh; Ld = g_Ql; }
        else if (p == 1) { Hd = g_Kh; Ld = g_Kl; }
        else             { Hd = g_Vh; Ld = g_Vl; }
        for (int i = tid; i < 512; i += 256) {
            int row = i >> 3, c8 = (i & 7) * 8;
            uint4 vh = reinterpret_cast<const uint4*>(sH)[i];
            uint4 vl = reinterpret_cast<const uint4*>(sL)[i];
            size_t off;
            if (p < 2) off = ((size_t)bh * TT + t0 + row) * DH + c8;
            else       off = ((size_t)bh * DH + row) * TT + t0 + c8;
            *reinterpret_cast<uint4*>(Hd + off) = vh;
            *reinterpret_cast<uint4*>(Ld + off) = vl;
        }
    }
}

// ---------------------------------------------------------------------------
// Kernel 2: flash attention (R11 version: Q in smem, single barrier per
// kv-iteration, load-after-sync). 256 threads (8 warps, 16q each).
// ---------------------------------------------------------------------------
#define ASTR 72
#define AQ_H 0
#define AQ_L (AQ_H + 128 * ASTR)
#define AKV  (AQ_L + 128 * ASTR)
#define AKV_STG (4 * 64 * ASTR)
#define A_MSK (AKV + 2 * AKV_STG)
#define ATTN_SMEM ((A_MSK + 1024) * 2)

__global__ __launch_bounds__(256) void attn_mma_kernel(const int* __restrict__ mask)
{
    extern __shared__ unsigned short shm[];
    int* sMask = (int*)(shm + A_MSK);
    uint32_t sb = (uint32_t)__cvta_generic_to_shared(shm);

    int tid = threadIdx.x;
    int wid = tid >> 5;
    int lane = tid & 31;
    int g = lane >> 2;
    int t = lane & 3;
    int wq = wid * 16;

    int bh = blockIdx.y;
    int b  = bh >> 4;
    int h  = bh & 15;
    int q0 = blockIdx.x * 128;

    int aRow  = (lane & 15);
    int aCol8 = (lane >> 4) * 8;
    int bRow  = ((lane >> 4) & 1) * 8 + (lane & 7);
    int bCol8 = ((lane >> 3) & 1) * 8;

    {
        const unsigned short* Qhg = g_Qh + ((size_t)bh * TT + q0) * DH;
        const unsigned short* Qlg = g_Ql + ((size_t)bh * TT + q0) * DH;
        for (int i = tid; i < 1024; i += 256) {
            int row = i >> 3, c8 = (i & 7) * 8;
            *reinterpret_cast<uint4*>(&shm[AQ_H + row * ASTR + c8]) =
                *reinterpret_cast<const uint4*>(Qhg + row * DH + c8);
            *reinterpret_cast<uint4*>(&shm[AQ_L + row * ASTR + c8]) =
                *reinterpret_cast<const uint4*>(Qlg + row * DH + c8);
        }
        for (int i = tid; i < TT; i += 256) sMask[i] = mask[b * TT + i];
    }

    auto load_kv = [&](int stage, int kb) {
        unsigned short* stg = shm + AKV + stage * AKV_STG;
        for (int i = tid; i < 512; i += 256) {
            int row = i >> 3, c8 = (i & 7) * 8;
            size_t ko = ((size_t)bh * TT + kb + row) * DH + c8;
            size_t vo = ((size_t)bh * DH + row) * TT + kb + c8;
            cp16(stg + row * ASTR + c8,         g_Kh + ko);
            cp16(stg + 4608 + row * ASTR + c8,  g_Kl + ko);
            cp16(stg + 9216 + row * ASTR + c8,  g_Vh + vo);
            cp16(stg + 13824 + row * ASTR + c8, g_Vl + vo);
        }
    };
    load_kv(0, 0);
    CP_COMMIT();

    float O[8][4];
    float m_[2], l_[2];
    m_[0] = m_[1] = -1e30f;
    l_[0] = l_[1] = 0.0f;
    #pragma unroll
    for (int nt = 0; nt < 8; nt++)
        #pragma unroll
        for (int r = 0; r < 4; r++) O[nt][r] = 0.0f;

    uint32_t qBase = sb + 2 * (AQ_H + (wq + aRow) * ASTR + aCol8);

    for (int kt = 0; kt < 8; kt++) {
        int kb = kt * 64;
        CP_WAIT0();          // stage kt resident
        __syncthreads();     // all warps done reading the buffer being overwritten

        if (kt + 1 < 8) {
            load_kv((kt + 1) & 1, kb + 64);
            CP_COMMIT();
        }

        uint32_t stgOff = 2 * (AKV + (kt & 1) * AKV_STG);
        uint32_t kBase = sb + stgOff + 2 * (bRow * ASTR + bCol8);
        uint32_t vBase = kBase + 2 * 9216;

        float S[8][4];
        #pragma unroll
        for (int nt = 0; nt < 8; nt++)
            #pragma unroll
            for (int r = 0; r < 4; r++) S[nt][r] = 0.0f;

        #pragma unroll
        for (int ks = 0; ks < 4; ks++) {
            uint32_t qh[4], ql[4];
            ldm_x4(qh, qBase + 32 * ks);
            ldm_x4(ql, qBase + 32 * ks + 2 * (AQ_L - AQ_H));
            uint32_t kh[16], kl[16];
            #pragma unroll
            for (int p = 0; p < 4; p++) {
                ldm_x4(&kh[4 * p], kBase + 2 * (p * 16 * ASTR + ks * 16));
                ldm_x4(&kl[4 * p], kBase + 2 * (p * 16 * ASTR + ks * 16 + 4608));
            }
            #pragma unroll
            for (int nt = 0; nt < 8; nt++) {
                mma16816(S[nt], qh, &kh[2 * nt]);
                mma16816(S[nt], qh, &kl[2 * nt]);
                mma16816(S[nt], ql, &kh[2 * nt]);
            }
        }

        #pragma unroll
        for (int nt = 0; nt < 8; nt++) {
            int mk0 = sMask[kb + nt * 8 + 2 * t];
            int mk1 = sMask[kb + nt * 8 + 2 * t + 1];
            if (mk0 <= 0) { S[nt][0] = -1e9f; S[nt][2] = -1e9f; }
            if (mk1 <= 0) { S[nt][1] = -1e9f; S[nt][3] = -1e9f; }
        }
        #pragma unroll
        for (int r = 0; r < 2; r++) {
            float mx = -1e30f;
            #pragma unroll
            for (int nt = 0; nt < 8; nt++) {
                mx = fmaxf(mx, S[nt][2 * r]);
                mx = fmaxf(mx, S[nt][2 * r + 1]);
            }
            mx = fmaxf(mx, __shfl_xor_sync(0xffffffffu, mx, 1));
            mx = fmaxf(mx, __shfl_xor_sync(0xffffffffu, mx, 2));
            float mnew  = fmaxf(m_[r], mx);
            float alpha = __expf(m_[r] - mnew);
            float rs = 0.0f;
            #pragma unroll
            for (int nt = 0; nt < 8; nt++) {
                float e0 = __expf(S[nt][2 * r]     - mnew);
                float e1 = __expf(S[nt][2 * r + 1] - mnew);
                S[nt][2 * r]     = e0;
                S[nt][2 * r + 1] = e1;
                rs += e0 + e1;
            }
            rs += __shfl_xor_sync(0xffffffffu, rs, 1);
            rs += __shfl_xor_sync(0xffffffffu, rs, 2);
            l_[r] = l_[r] * alpha + rs;
            m_[r] = mnew;
            #pragma unroll
            for (int nt = 0; nt < 8; nt++) {
                O[nt][2 * r]     *= alpha;
                O[nt][2 * r + 1] *= alpha;
            }
        }

        #pragma unroll
        for (int ks = 0; ks < 4; ks++) {
            uint32_t ph[4], pl[4];
            #pragma unroll
            for (int half = 0; half < 2; half++) {
                const float* sv = S[2 * ks + half];
                uint32_t b0 = __float_as_uint(sv[0]);
                uint32_t b1 = __float_as_uint(sv[1]);
                uint32_t b2 = __float_as_uint(sv[2]);
                uint32_t b3 = __float_as_uint(sv[3]);
                ph[2 * half]     = __byte_perm(b0, b1, 0x7632);
                ph[2 * half + 1] = __byte_perm(b2, b3, 0x7632);
                float l0 = sv[0] - __uint_as_float(b0 & 0xFFFF0000u);
                float l1 = sv[1] - __uint_as_float(b1 & 0xFFFF0000u);
                float l2 = sv[2] - __uint_as_float(b2 & 0xFFFF0000u);
                float l3 = sv[3] - __uint_as_float(b3 & 0xFFFF0000u);
                asm("cvt.rn.bf16x2.f32 %0, %1, %2;"
                    : "=r"(pl[2 * half]) : "f"(l1), "f"(l0));
                asm("cvt.rn.bf16x2.f32 %0, %1, %2;"
                    : "=r"(pl[2 * half + 1]) : "f"(l3), "f"(l2));
            }
            uint32_t vh[16], vl[16];
            #pragma unroll
            for (int p = 0; p < 4; p++) {
                ldm_x4(&vh[4 * p], vBase + 2 * (p * 16 * ASTR + ks * 16));
                ldm_x4(&vl[4 * p], vBase + 2 * (p * 16 * ASTR + ks * 16 + 4608));
            }
            #pragma unroll
            for (int nt = 0; nt < 8; nt++) {
                mma16816(O[nt], ph, &vh[2 * nt]);
                mma16816(O[nt], ph, &vl[2 * nt]);
                mma16816(O[nt], pl, &vh[2 * nt]);
            }
        }
    }

    #pragma unroll
    for (int r = 0; r < 2; r++) {
        float inv = 1.0f / l_[r];
        int mrow = b * TT + q0 + wq + g + 8 * r;
        size_t base = (size_t)mrow * DD + h * DH;
        #pragma unroll
        for (int nt = 0; nt < 8; nt++) {
            float v0 = O[nt][2 * r]     * inv;
            float v1 = O[nt][2 * r + 1] * inv;
            uint32_t b0 = __float_as_uint(v0), b1 = __float_as_uint(v1);
            uint32_t hp = __byte_perm(b0, b1, 0x7632);
            float l0 = v0 - __uint_as_float(b0 & 0xFFFF0000u);
            float l1 = v1 - __uint_as_float(b1 & 0xFFFF0000u);
            uint32_t lp;
            asm("cvt.rn.bf16x2.f32 %0, %1, %2;" : "=r"(lp) : "f"(l1), "f"(l0));
            *reinterpret_cast<uint32_t*>(g_Ah + base + nt * 8 + 2 * t) = hp;
            *reinterpret_cast<uint32_t*>(g_Al + base + nt * 8 + 2 * t) = lp;
        }
    }
}

// ---------------------------------------------------------------------------
// Kernel 3: Wf [k][n] fp32 -> g_Wh/g_Wl [n][k] bf16 (transpose + split)
// ---------------------------------------------------------------------------
__global__ __launch_bounds__(256) void convW_kernel(const float* __restrict__ Wf)
{
    __shared__ float t[32][33];
    int k0 = blockIdx.x * 32, n0 = blockIdx.y * 32;
    int tx = threadIdx.x & 31, ty = threadIdx.x >> 5;
    #pragma unroll
    for (int j = 0; j < 4; j++)
        t[ty + 8 * j][tx] = Wf[(size_t)(k0 + ty + 8 * j) * DD + n0 + tx];
    __syncthreads();
    #pragma unroll
    for (int j = 0; j < 4; j++) {
        int k = k0 + tx, n = n0 + ty + 8 * j;
        float v = t[tx][ty + 8 * j];
        unsigned short hh, ll;
        fsplit(v, hh, ll);
        g_Wh[(size_t)n * DD + k] = hh;
        g_Wl[(size_t)n * DD + k] = ll;
    }
}

// ---------------------------------------------------------------------------
// Kernel 4: fusion GEMM (R8/R12 measured-best: compute, then prefetch).
// CTA 128m x 64n, 8 warps 4m x 2n, BK=32, 3-stage cp.async, 2 CTAs/SM.
// ---------------------------------------------------------------------------
#define F2 40
#define FST_A  (128 * F2)
#define FST_B  (64 * F2)
#define FST_SZ (2 * FST_A + 2 * FST_B)
#define FNST 3
#define FUSE_SMEM (FNST * FST_SZ * 2)

__global__ __launch_bounds__(256, 2) void fuse_mma_kernel(
    const float* __restrict__ bf, float* __restrict__ C)
{
    extern __shared__ unsigned short fsm[];
    uint32_t sb = (uint32_t)__cvta_generic_to_shared(fsm);

    int tid = threadIdx.x;
    int wid = tid >> 5;
    int lane = tid & 31;
    int g = lane >> 2;
    int t = lane & 3;
    int wm = wid >> 1;
    int wn = wid & 1;

    int n0 = blockIdx.x * 64;
    int m0 = blockIdx.y * 128;

    int aRow  = (lane & 15);
    int aCol8 = (lane >> 4) * 8;
    int bRow  = ((lane >> 4) & 1) * 8 + (lane & 7);
    int bCol8 = ((lane >> 3) & 1) * 8;

    auto load_stage = [&](int stage, int k0) {
        unsigned short* st = fsm + stage * FST_SZ;
        for (int i = tid; i < 512; i += 256) {
            int row = i >> 2, c = (i & 3) * 8;
            size_t ga = (size_t)(m0 + row) * DD + k0 + c;
            cp16(st + row * F2 + c,          g_Ah + ga);
            cp16(st + FST_A + row * F2 + c,  g_Al + ga);
        }
        {
            int i = tid & 255;
            int row = i >> 2, c = (i & 3) * 8;
            size_t gb = (size_t)(n0 + row) * DD + k0 + c;
            cp16(st + 2 * FST_A + row * F2 + c,          g_Wh + gb);
            cp16(st + 2 * FST_A + FST_B + row * F2 + c,  g_Wl + gb);
        }
    };

    float acc[2][4][4];
    #pragma unroll
    for (int mt = 0; mt < 2; mt++)
        #pragma unroll
        for (int nt = 0; nt < 4; nt++)
            #pragma unroll
            for (int r = 0; r < 4; r++) acc[mt][nt][r] = 0.0f;

    load_stage(0, 0);
    CP_COMMIT();
    load_stage(1, 32);
    CP_COMMIT();

    uint32_t aBaseRow = 2 * ((wm * 32 + aRow) * F2 + aCol8);
    uint32_t bBaseRow = 2 * ((wn * 32 + bRow) * F2 + bCol8);

    for (int kt = 0; kt < 32; kt++) {
        CP_WAIT1();
        __syncthreads();

        uint32_t stOff = sb + (uint32_t)((kt % 3) * FST_SZ) * 2;

        #pragma unroll
        for (int ks = 0; ks < 2; ks++) {
            int k = ks * 16;
            uint32_t ah[2][4], al[2][4];
            #pragma unroll
            for (int mt = 0; mt < 2; mt++) {
                uint32_t ua = stOff + aBaseRow + 2 * (mt * 16 * F2 + k);
                ldm_x4(ah[mt], ua);
                ldm_x4(al[mt], ua + 2 * FST_A);
            }
            uint32_t bh[8], blo[8];
            #pragma unroll
            for (int p = 0; p < 2; p++) {
                uint32_t ub = stOff + bBaseRow + 2 * (2 * FST_A + p * 16 * F2 + k);
                ldm_x4(&bh[4 * p], ub);
                ldm_x4(&blo[4 * p], ub + 2 * FST_B);
            }
            #pragma unroll
            for (int mt = 0; mt < 2; mt++)
                #pragma unroll
                for (int nt = 0; nt < 4; nt++) {
                    mma16816(acc[mt][nt], ah[mt], &bh[2 * nt]);
                    mma16816(acc[mt][nt], ah[mt], &blo[2 * nt]);
                    mma16816(acc[mt][nt], al[mt], &bh[2 * nt]);
                }
        }
        __syncthreads();

        if (kt + 2 < 32) load_stage((kt + 2) % 3, (kt + 2) * 32);
        CP_COMMIT();
    }

    #pragma unroll
    for (int nt = 0; nt < 4; nt++) {
        int n = n0 + wn * 32 + nt * 8 + t * 2;
        float b0 = bf[n], b1 = bf[n + 1];
        #pragma unroll
        for (int mt = 0; mt < 2; mt++) {
            int m = m0 + wm * 32 + mt * 16 + g;
            float2 v0 = make_float2(acc[mt][nt][0] + b0, acc[mt][nt][1] + b1);
            float2 v1 = make_float2(acc[mt][nt][2] + b0, acc[mt][nt][3] + b1);
            *reinterpret_cast<float2*>(C + (size_t)m * DD + n) = v0;
            *reinterpret_cast<float2*>(C + (size_t)(m + 8) * DD + n) = v1;
        }
    }
}

// ---------------------------------------------------------------------------
extern "C" void kernel_launch(void* const* d_in, const int* in_sizes, int n_in,
                              void* d_out, int out_size)
{
    const float* X    = (const float*)d_in[0];
    const int*   mask = (const int*)  d_in[1];
    const float* Wq   = (const float*)d_in[2];
    const float* bq   = (const float*)d_in[3];
    const float* Wk   = (const float*)d_in[4];
    const float* bk   = (const float*)d_in[5];
    const float* Wv   = (const float*)d_in[6];
    const float* bv   = (const float*)d_in[7];
    const float* Wf   = (const float*)d_in[8];
    const float* bf   = (const float*)d_in[9];
    float* out = (float*)d_out;

    cudaFuncSetAttribute(qkv_kernel,
                         cudaFuncAttributeMaxDynamicSharedMemorySize, QKV_SMEM);
    cudaFuncSetAttribute(attn_mma_kernel,
                         cudaFuncAttributeMaxDynamicSharedMemorySize, ATTN_SMEM);
    cudaFuncSetAttribute(fuse_mma_kernel,
                         cudaFuncAttributeMaxDynamicSharedMemorySize, FUSE_SMEM);

    dim3 grid1(TT / 64, BB * HH);
    qkv_kernel<<<grid1, 256, QKV_SMEM>>>(X, Wq, bq, Wk, bk, Wv, bv);

    convW_kernel<<<dim3(32, 32), 256>>>(Wf);

    dim3 grid2(TT / 128, BB * HH);
    attn_mma_kernel<<<grid2, 256, ATTN_SMEM>>>(mask);

    dim3 grid4(DD / 64, (BB * TT) / 128);
    fuse_mma_kernel<<<grid4, 256, FUSE_SMEM>>>(bf, out);
}

// round 15
// speedup vs baseline: 1.1072x; 1.0320x over previous
#include <cuda_runtime.h>
#include <cuda_bf16.h>
#include <cstdint>

#define BB 8
#define TT 512
#define DD 1024
#define HH 16
#define DH 64

// bf16 hi/lo splits (device globals; no allocs allowed)
__device__ unsigned short g_Qh[BB * HH * TT * DH];   // [bh][t][d]  (Q pre-scaled by 1/8)
__device__ unsigned short g_Ql[BB * HH * TT * DH];
__device__ unsigned short g_Kh[BB * HH * TT * DH];   // [bh][t][d]
__device__ unsigned short g_Kl[BB * HH * TT * DH];
__device__ unsigned short g_Vh[BB * HH * TT * DH];   // [bh][t][d]  (NEW: same as K)
__device__ unsigned short g_Vl[BB * HH * TT * DH];
__device__ unsigned short g_Ah[BB * TT * DD];        // attention out split [m][k]
__device__ unsigned short g_Al[BB * TT * DD];
__device__ unsigned short g_Wh[DD * DD];             // Wf^T: [n][k]
__device__ unsigned short g_Wl[DD * DD];
__device__ unsigned short g_W3h[3 * HH * DH * DH];   // QKV weights^T: [p][h][e][d]
__device__ unsigned short g_W3l[3 * HH * DH * DH];

__device__ __forceinline__ void mma16816(float* c, const uint32_t* a, const uint32_t* b) {
    asm volatile(
        "mma.sync.aligned.m16n8k16.row.col.f32.bf16.bf16.f32 "
        "{%0,%1,%2,%3}, {%4,%5,%6,%7}, {%8,%9}, {%0,%1,%2,%3};"
        : "+f"(c[0]), "+f"(c[1]), "+f"(c[2]), "+f"(c[3])
        : "r"(a[0]), "r"(a[1]), "r"(a[2]), "r"(a[3]), "r"(b[0]), "r"(b[1]));
}

__device__ __forceinline__ void ldm_x4(uint32_t* r, uint32_t saddr) {
    asm volatile("ldmatrix.sync.aligned.m8n8.x4.shared.b16 {%0,%1,%2,%3}, [%4];"
        : "=r"(r[0]), "=r"(r[1]), "=r"(r[2]), "=r"(r[3]) : "r"(saddr));
}
__device__ __forceinline__ void ldm_x4t(uint32_t* r, uint32_t saddr) {
    asm volatile("ldmatrix.sync.aligned.m8n8.x4.trans.shared.b16 {%0,%1,%2,%3}, [%4];"
        : "=r"(r[0]), "=r"(r[1]), "=r"(r[2]), "=r"(r[3]) : "r"(saddr));
}

__device__ __forceinline__ void fsplit(float v, unsigned short& h, unsigned short& l) {
    uint32_t b = __float_as_uint(v);
    h = (unsigned short)(b >> 16);
    float lo = v - __uint_as_float(b & 0xFFFF0000u);
    uint32_t p;
    asm("cvt.rn.bf16x2.f32 %0, %1, %2;" : "=r"(p) : "f"(lo), "f"(lo));
    l = (unsigned short)(p & 0xFFFF);
}

__device__ __forceinline__ void cp16(unsigned short* sdst, const unsigned short* gsrc) {
    uint32_t s = (uint32_t)__cvta_generic_to_shared(sdst);
    asm volatile("cp.async.cg.shared.global [%0], [%1], 16;" :: "r"(s), "l"(gsrc));
}
#define CP_COMMIT() asm volatile("cp.async.commit_group;" ::: "memory")
#define CP_WAIT1()  asm volatile("cp.async.wait_group 1;" ::: "memory")
#define CP_WAIT0()  asm volatile("cp.async.wait_group 0;" ::: "memory")

// ---------------------------------------------------------------------------
// Kernel 0: Wq/Wk/Wv [h][d][e] fp32 -> g_W3h/g_W3l [p][h][e][d] bf16 splits
// grid (3, 16), 256 threads.
// ---------------------------------------------------------------------------
__global__ __launch_bounds__(256) void convW3_kernel(
    const float* __restrict__ Wq, const float* __restrict__ Wk,
    const float* __restrict__ Wv)
{
    __shared__ float tile[64][65];
    int p = blockIdx.x;
    int h = blockIdx.y;
    int tid = threadIdx.x;
    const float* W = (p == 0 ? Wq : (p == 1 ? Wk : Wv)) + h * DH * DH;  // [d][e]
    for (int i = tid; i < 4096; i += 256) {
        int d = i >> 6, e = i & 63;
        tile[d][e] = W[i];
    }
    __syncthreads();
    unsigned short* Hd = g_W3h + (size_t)(p * HH + h) * DH * DH;  // [e][d]
    unsigned short* Ld = g_W3l + (size_t)(p * HH + h) * DH * DH;
    for (int i = tid; i < 4096; i += 256) {
        int e = i >> 6, d = i & 63;
        unsigned short hh, ll;
        fsplit(tile[d][e], hh, ll);
        Hd[i] = hh;
        Ld[i] = ll;
    }
}

// ---------------------------------------------------------------------------
// Kernel 1: QKV projections via mma.sync bf16-split.
// grid (T/128, B*H), 256 threads (8 warps, 16 t-rows each).
// ---------------------------------------------------------------------------
#define QSTR 72
#define QM_XH 0
#define QM_XL (128 * QSTR)                 // 9216
#define QM_W  (2 * 128 * QSTR)            // 18432 (6 matrices of 64*72: p0h p0l p1h p1l p2h p2l)
#define QM_WSZ (64 * QSTR)                // 4608
#define QM_BIAS (QM_W + 6 * QM_WSZ)       // 46080 (ushort idx); 192 floats = 384 slots
#define QKV_SMEM ((QM_BIAS + 384) * 2)

__global__ __launch_bounds__(256) void qkv_mma_kernel(
    const float* __restrict__ X,
    const float* __restrict__ bq, const float* __restrict__ bk,
    const float* __restrict__ bv)
{
    extern __shared__ unsigned short shq[];
    uint32_t sb = (uint32_t)__cvta_generic_to_shared(shq);
    float* sBias = (float*)(shq + QM_BIAS);

    int tid = threadIdx.x;
    int wid = tid >> 5;
    int lane = tid & 31;
    int g = lane >> 2;
    int t = lane & 3;
    int wq = wid * 16;

    int bh = blockIdx.y;
    int b  = bh >> 4;
    int h  = bh & 15;
    int t0 = blockIdx.x * 128;

    int aRow  = (lane & 15);
    int aCol8 = (lane >> 4) * 8;
    int bRow  = ((lane >> 4) & 1) * 8 + (lane & 7);
    int bCol8 = ((lane >> 3) & 1) * 8;

    // async weight loads: 6 matrices [e][d] 64x64 -> stride-72 smem
    #pragma unroll
    for (int m = 0; m < 6; m++) {
        const unsigned short* src =
            ((m & 1) ? g_W3l : g_W3h) + (size_t)((m >> 1) * HH + h) * DH * DH;
        for (int i = tid; i < 512; i += 256) {
            int row = i >> 3, c8 = (i & 7) * 8;
            cp16(shq + QM_W + m * QM_WSZ + row * QSTR + c8, src + row * DH + c8);
        }
    }
    CP_COMMIT();

    // bias
    if (tid < 192) {
        int p = tid >> 6, e = tid & 63;
        const float* bb = (p == 0) ? bq : (p == 1 ? bk : bv);
        sBias[tid] = bb[h * DH + e];
    }

    // X load + split into Xh/Xl smem (A-operand [t][d], stride 72)
    const float* Xb = X + ((size_t)(b * TT + t0)) * DD + h * DH;
    for (int i = tid; i < 2048; i += 256) {
        int row = i >> 4, d4 = (i & 15) * 4;
        float4 v = *reinterpret_cast<const float4*>(Xb + (size_t)row * DD + d4);
        uint32_t bx = __float_as_uint(v.x), by = __float_as_uint(v.y);
        uint32_t bz = __float_as_uint(v.z), bw = __float_as_uint(v.w);
        uint32_t h01 = __byte_perm(bx, by, 0x7632);
        uint32_t h23 = __byte_perm(bz, bw, 0x7632);
        float l0 = v.x - __uint_as_float(bx & 0xFFFF0000u);
        float l1 = v.y - __uint_as_float(by & 0xFFFF0000u);
        float l2 = v.z - __uint_as_float(bz & 0xFFFF0000u);
        float l3 = v.w - __uint_as_float(bw & 0xFFFF0000u);
        uint32_t p01, p23;
        asm("cvt.rn.bf16x2.f32 %0, %1, %2;" : "=r"(p01) : "f"(l1), "f"(l0));
        asm("cvt.rn.bf16x2.f32 %0, %1, %2;" : "=r"(p23) : "f"(l3), "f"(l2));
        *reinterpret_cast<uint2*>(&shq[QM_XH + row * QSTR + d4]) = make_uint2(h01, h23);
        *reinterpret_cast<uint2*>(&shq[QM_XL + row * QSTR + d4]) = make_uint2(p01, p23);
    }
    CP_WAIT0();
    __syncthreads();

    // hoist A fragments (loop-invariant across the 3 outputs)
    uint32_t xh[4][4], xl[4][4];
    {
        uint32_t aBase = sb + 2 * (QM_XH + (wq + aRow) * QSTR + aCol8);
        #pragma unroll
        for (int ks = 0; ks < 4; ks++) {
            ldm_x4(xh[ks], aBase + 32 * ks);
            ldm_x4(xl[ks], aBase + 2 * (QM_XL - QM_XH) + 32 * ks);
        }
    }

    #pragma unroll
    for (int p = 0; p < 3; p++) {
        float acc[8][4];
        #pragma unroll
        for (int nt = 0; nt < 8; nt++)
            #pragma unroll
            for (int r = 0; r < 4; r++) acc[nt][r] = 0.0f;

        uint32_t bB = sb + 2 * (QM_W + (2 * p) * QM_WSZ + bRow * QSTR + bCol8);
        #pragma unroll
        for (int ks = 0; ks < 4; ks++) {
            uint32_t wh[16], wl[16];
            #pragma unroll
            for (int pp = 0; pp < 4; pp++) {
                ldm_x4(&wh[4 * pp], bB + 2 * (pp * 16 * QSTR + ks * 16));
                ldm_x4(&wl[4 * pp], bB + 2 * (QM_WSZ + pp * 16 * QSTR + ks * 16));
            }
            #pragma unroll
            for (int nt = 0; nt < 8; nt++) {
                mma16816(acc[nt], xh[ks], &wh[2 * nt]);
                mma16816(acc[nt], xh[ks], &wl[2 * nt]);
                mma16816(acc[nt], xl[ks], &wh[2 * nt]);
            }
        }

        float qs = (p == 0) ? 0.125f : 1.0f;
        unsigned short* Hd = (p == 0) ? g_Qh : (p == 1 ? g_Kh : g_Vh);
        unsigned short* Ld = (p == 0) ? g_Ql : (p == 1 ? g_Kl : g_Vl);
        #pragma unroll
        for (int r = 0; r < 2; r++) {
            int row = t0 + wq + g + 8 * r;
            size_t base = ((size_t)bh * TT + row) * DH;
            #pragma unroll
            for (int nt = 0; nt < 8; nt++) {
                int col = nt * 8 + 2 * t;
                float v0 = (acc[nt][2 * r]     + sBias[p * 64 + col])     * qs;
                float v1 = (acc[nt][2 * r + 1] + sBias[p * 64 + col + 1]) * qs;
                uint32_t b0 = __float_as_uint(v0), b1 = __float_as_uint(v1);
                uint32_t hp = __byte_perm(b0, b1, 0x7632);
                float l0 = v0 - __uint_as_float(b0 & 0xFFFF0000u);
                float l1 = v1 - __uint_as_float(b1 & 0xFFFF0000u);
                uint32_t lp;
                asm("cvt.rn.bf16x2.f32 %0, %1, %2;" : "=r"(lp) : "f"(l1), "f"(l0));
                *reinterpret_cast<uint32_t*>(Hd + base + col) = hp;
                *reinterpret_cast<uint32_t*>(Ld + base + col) = lp;
            }
        }
    }
}

// ---------------------------------------------------------------------------
// Kernel 2: flash attention (R11 config; V now [t][d] via ldmatrix.trans).
// ---------------------------------------------------------------------------
#define ASTR 72
#define AQ_H 0
#define AQ_L (AQ_H + 128 * ASTR)
#define AKV  (AQ_L + 128 * ASTR)
#define AKV_STG (4 * 64 * ASTR)
#define A_MSK (AKV + 2 * AKV_STG)
#define ATTN_SMEM ((A_MSK + 1024) * 2)

__global__ __launch_bounds__(256) void attn_mma_kernel(const int* __restrict__ mask)
{
    extern __shared__ unsigned short shm[];
    int* sMask = (int*)(shm + A_MSK);
    uint32_t sb = (uint32_t)__cvta_generic_to_shared(shm);

    int tid = threadIdx.x;
    int wid = tid >> 5;
    int lane = tid & 31;
    int g = lane >> 2;
    int t = lane & 3;
    int wq = wid * 16;

    int bh = blockIdx.y;
    int b  = bh >> 4;
    int h  = bh & 15;
    int q0 = blockIdx.x * 128;

    int aRow  = (lane & 15);
    int aCol8 = (lane >> 4) * 8;
    int bRow  = ((lane >> 4) & 1) * 8 + (lane & 7);
    int bCol8 = ((lane >> 3) & 1) * 8;
    // trans-ldmatrix per-lane mapping for V (rows = key, cols = d)
    int oct   = lane >> 3;
    int vRow  = (oct & 1) * 8 + (lane & 7);
    int vCol8 = (oct >> 1) * 8;

    {
        const unsigned short* Qhg = g_Qh + ((size_t)bh * TT + q0) * DH;
        const unsigned short* Qlg = g_Ql + ((size_t)bh * TT + q0) * DH;
        for (int i = tid; i < 1024; i += 256) {
            int row = i >> 3, c8 = (i & 7) * 8;
            *reinterpret_cast<uint4*>(&shm[AQ_H + row * ASTR + c8]) =
                *reinterpret_cast<const uint4*>(Qhg + row * DH + c8);
            *reinterpret_cast<uint4*>(&shm[AQ_L + row * ASTR + c8]) =
                *reinterpret_cast<const uint4*>(Qlg + row * DH + c8);
        }
        for (int i = tid; i < TT; i += 256) sMask[i] = mask[b * TT + i];
    }

    auto load_kv = [&](int stage, int kb) {
        unsigned short* stg = shm + AKV + stage * AKV_STG;
        for (int i = tid; i < 512; i += 256) {
            int row = i >> 3, c8 = (i & 7) * 8;
            size_t ko = ((size_t)bh * TT + kb + row) * DH + c8;
            cp16(stg + row * ASTR + c8,         g_Kh + ko);
            cp16(stg + 4608 + row * ASTR + c8,  g_Kl + ko);
            cp16(stg + 9216 + row * ASTR + c8,  g_Vh + ko);
            cp16(stg + 13824 + row * ASTR + c8, g_Vl + ko);
        }
    };
    load_kv(0, 0);
    CP_COMMIT();

    float O[8][4];
    float m_[2], l_[2];
    m_[0] = m_[1] = -1e30f;
    l_[0] = l_[1] = 0.0f;
    #pragma unroll
    for (int nt = 0; nt < 8; nt++)
        #pragma unroll
        for (int r = 0; r < 4; r++) O[nt][r] = 0.0f;

    uint32_t qBase = sb + 2 * (AQ_H + (wq + aRow) * ASTR + aCol8);

    for (int kt = 0; kt < 8; kt++) {
        int kb = kt * 64;
        CP_WAIT0();
        __syncthreads();

        if (kt + 1 < 8) {
            load_kv((kt + 1) & 1, kb + 64);
            CP_COMMIT();
        }

        uint32_t stgOff = 2 * (AKV + (kt & 1) * AKV_STG);
        uint32_t kBase = sb + stgOff + 2 * (bRow * ASTR + bCol8);
        uint32_t vBase = sb + stgOff + 2 * (9216 + vRow * ASTR + vCol8);

        float S[8][4];
        #pragma unroll
        for (int nt = 0; nt < 8; nt++)
            #pragma unroll
            for (int r = 0; r < 4; r++) S[nt][r] = 0.0f;

        #pragma unroll
        for (int ks = 0; ks < 4; ks++) {
            uint32_t qh[4], ql[4];
            ldm_x4(qh, qBase + 32 * ks);
            ldm_x4(ql, qBase + 32 * ks + 2 * (AQ_L - AQ_H));
            uint32_t kh[16], kl[16];
            #pragma unroll
            for (int p = 0; p < 4; p++) {
                ldm_x4(&kh[4 * p], kBase + 2 * (p * 16 * ASTR + ks * 16));
                ldm_x4(&kl[4 * p], kBase + 2 * (p * 16 * ASTR + ks * 16 + 4608));
            }
            #pragma unroll
            for (int nt = 0; nt < 8; nt++) {
                mma16816(S[nt], qh, &kh[2 * nt]);
                mma16816(S[nt], qh, &kl[2 * nt]);
                mma16816(S[nt], ql, &kh[2 * nt]);
            }
        }

        #pragma unroll
        for (int nt = 0; nt < 8; nt++) {
            int mk0 = sMask[kb + nt * 8 + 2 * t];
            int mk1 = sMask[kb + nt * 8 + 2 * t + 1];
            if (mk0 <= 0) { S[nt][0] = -1e9f; S[nt][2] = -1e9f; }
            if (mk1 <= 0) { S[nt][1] = -1e9f; S[nt][3] = -1e9f; }
        }
        #pragma unroll
        for (int r = 0; r < 2; r++) {
            float mx = -1e30f;
            #pragma unroll
            for (int nt = 0; nt < 8; nt++) {
                mx = fmaxf(mx, S[nt][2 * r]);
                mx = fmaxf(mx, S[nt][2 * r + 1]);
            }
            mx = fmaxf(mx, __shfl_xor_sync(0xffffffffu, mx, 1));
            mx = fmaxf(mx, __shfl_xor_sync(0xffffffffu, mx, 2));
            float mnew  = fmaxf(m_[r], mx);
            float alpha = __expf(m_[r] - mnew);
            float rs = 0.0f;
            #pragma unroll
            for (int nt = 0; nt < 8; nt++) {
                float e0 = __expf(S[nt][2 * r]     - mnew);
                float e1 = __expf(S[nt][2 * r + 1] - mnew);
                S[nt][2 * r]     = e0;
                S[nt][2 * r + 1] = e1;
                rs += e0 + e1;
            }
            rs += __shfl_xor_sync(0xffffffffu, rs, 1);
            rs += __shfl_xor_sync(0xffffffffu, rs, 2);
            l_[r] = l_[r] * alpha + rs;
            m_[r] = mnew;
            #pragma unroll
            for (int nt = 0; nt < 8; nt++) {
                O[nt][2 * r]     *= alpha;
                O[nt][2 * r + 1] *= alpha;
            }
        }

        #pragma unroll
        for (int ks = 0; ks < 4; ks++) {
            uint32_t ph[4], pl[4];
            #pragma unroll
            for (int half = 0; half < 2; half++) {
                const float* sv = S[2 * ks + half];
                uint32_t b0 = __float_as_uint(sv[0]);
                uint32_t b1 = __float_as_uint(sv[1]);
                uint32_t b2 = __float_as_uint(sv[2]);
                uint32_t b3 = __float_as_uint(sv[3]);
                ph[2 * half]     = __byte_perm(b0, b1, 0x7632);
                ph[2 * half + 1] = __byte_perm(b2, b3, 0x7632);
                float l0 = sv[0] - __uint_as_float(b0 & 0xFFFF0000u);
                float l1 = sv[1] - __uint_as_float(b1 & 0xFFFF0000u);
                float l2 = sv[2] - __uint_as_float(b2 & 0xFFFF0000u);
                float l3 = sv[3] - __uint_as_float(b3 & 0xFFFF0000u);
                asm("cvt.rn.bf16x2.f32 %0, %1, %2;"
                    : "=r"(pl[2 * half]) : "f"(l1), "f"(l0));
                asm("cvt.rn.bf16x2.f32 %0, %1, %2;"
                    : "=r"(pl[2 * half + 1]) : "f"(l3), "f"(l2));
            }
            uint32_t vh[16], vl[16];
            #pragma unroll
            for (int p = 0; p < 4; p++) {
                ldm_x4t(&vh[4 * p], vBase + 2 * (ks * 16 * ASTR + p * 16));
                ldm_x4t(&vl[4 * p], vBase + 2 * (ks * 16 * ASTR + p * 16 + 4608));
            }
            #pragma unroll
            for (int nt = 0; nt < 8; nt++) {
                mma16816(O[nt], ph, &vh[2 * nt]);
                mma16816(O[nt], ph, &vl[2 * nt]);
                mma16816(O[nt], pl, &vh[2 * nt]);
            }
        }
    }

    #pragma unroll
    for (int r = 0; r < 2; r++) {
        float inv = 1.0f / l_[r];
        int mrow = b * TT + q0 + wq + g + 8 * r;
        size_t base = (size_t)mrow * DD + h * DH;
        #pragma unroll
        for (int nt = 0; nt < 8; nt++) {
            float v0 = O[nt][2 * r]     * inv;
            float v1 = O[nt][2 * r + 1] * inv;
            uint32_t b0 = __float_as_uint(v0), b1 = __float_as_uint(v1);
            uint32_t hp = __byte_perm(b0, b1, 0x7632);
            float l0 = v0 - __uint_as_float(b0 & 0xFFFF0000u);
            float l1 = v1 - __uint_as_float(b1 & 0xFFFF0000u);
            uint32_t lp;
            asm("cvt.rn.bf16x2.f32 %0, %1, %2;" : "=r"(lp) : "f"(l1), "f"(l0));
            *reinterpret_cast<uint32_t*>(g_Ah + base + nt * 8 + 2 * t) = hp;
            *reinterpret_cast<uint32_t*>(g_Al + base + nt * 8 + 2 * t) = lp;
        }
    }
}

// ---------------------------------------------------------------------------
// Kernel 3: Wf [k][n] fp32 -> g_Wh/g_Wl [n][k] bf16 (transpose + split)
// ---------------------------------------------------------------------------
__global__ __launch_bounds__(256) void convW_kernel(const float* __restrict__ Wf)
{
    __shared__ float t[32][33];
    int k0 = blockIdx.x * 32, n0 = blockIdx.y * 32;
    int tx = threadIdx.x & 31, ty = threadIdx.x >> 5;
    #pragma unroll
    for (int j = 0; j < 4; j++)
        t[ty + 8 * j][tx] = Wf[(size_t)(k0 + ty + 8 * j) * DD + n0 + tx];
    __syncthreads();
    #pragma unroll
    for (int j = 0; j < 4; j++) {
        int k = k0 + tx, n = n0 + ty + 8 * j;
        float v = t[tx][ty + 8 * j];
        unsigned short hh, ll;
        fsplit(v, hh, ll);
        g_Wh[(size_t)n * DD + k] = hh;
        g_Wl[(size_t)n * DD + k] = ll;
    }
}

// ---------------------------------------------------------------------------
// Kernel 4: fusion GEMM (R8/R12 measured-best).
// ---------------------------------------------------------------------------
#define F2 40
#define FST_A  (128 * F2)
#define FST_B  (64 * F2)
#define FST_SZ (2 * FST_A + 2 * FST_B)
#define FNST 3
#define FUSE_SMEM (FNST * FST_SZ * 2)

__global__ __launch_bounds__(256, 2) void fuse_mma_kernel(
    const float* __restrict__ bf, float* __restrict__ C)
{
    extern __shared__ unsigned short fsm[];
    uint32_t sb = (uint32_t)__cvta_generic_to_shared(fsm);

    int tid = threadIdx.x;
    int wid = tid >> 5;
    int lane = tid & 31;
    int g = lane >> 2;
    int t = lane & 3;
    int wm = wid >> 1;
    int wn = wid & 1;

    int n0 = blockIdx.x * 64;
    int m0 = blockIdx.y * 128;

    int aRow  = (lane & 15);
    int aCol8 = (lane >> 4) * 8;
    int bRow  = ((lane >> 4) & 1) * 8 + (lane & 7);
    int bCol8 = ((lane >> 3) & 1) * 8;

    auto load_stage = [&](int stage, int k0) {
        unsigned short* st = fsm + stage * FST_SZ;
        for (int i = tid; i < 512; i += 256) {
            int row = i >> 2, c = (i & 3) * 8;
            size_t ga = (size_t)(m0 + row) * DD + k0 + c;
            cp16(st + row * F2 + c,          g_Ah + ga);
            cp16(st + FST_A + row * F2 + c,  g_Al + ga);
        }
        {
            int i = tid & 255;
            int row = i >> 2, c = (i & 3) * 8;
            size_t gb = (size_t)(n0 + row) * DD + k0 + c;
            cp16(st + 2 * FST_A + row * F2 + c,          g_Wh + gb);
            cp16(st + 2 * FST_A + FST_B + row * F2 + c,  g_Wl + gb);
        }
    };

    float acc[2][4][4];
    #pragma unroll
    for (int mt = 0; mt < 2; mt++)
        #pragma unroll
        for (int nt = 0; nt < 4; nt++)
            #pragma unroll
            for (int r = 0; r < 4; r++) acc[mt][nt][r] = 0.0f;

    load_stage(0, 0);
    CP_COMMIT();
    load_stage(1, 32);
    CP_COMMIT();

    uint32_t aBaseRow = 2 * ((wm * 32 + aRow) * F2 + aCol8);
    uint32_t bBaseRow = 2 * ((wn * 32 + bRow) * F2 + bCol8);

    for (int kt = 0; kt < 32; kt++) {
        CP_WAIT1();
        __syncthreads();

        uint32_t stOff = sb + (uint32_t)((kt % 3) * FST_SZ) * 2;

        #pragma unroll
        for (int ks = 0; ks < 2; ks++) {
            int k = ks * 16;
            uint32_t ah[2][4], al[2][4];
            #pragma unroll
            for (int mt = 0; mt < 2; mt++) {
                uint32_t ua = stOff + aBaseRow + 2 * (mt * 16 * F2 + k);
                ldm_x4(ah[mt], ua);
                ldm_x4(al[mt], ua + 2 * FST_A);
            }
            uint32_t bh[8], blo[8];
            #pragma unroll
            for (int p = 0; p < 2; p++) {
                uint32_t ub = stOff + bBaseRow + 2 * (2 * FST_A + p * 16 * F2 + k);
                ldm_x4(&bh[4 * p], ub);
                ldm_x4(&blo[4 * p], ub + 2 * FST_B);
            }
            #pragma unroll
            for (int mt = 0; mt < 2; mt++)
                #pragma unroll
                for (int nt = 0; nt < 4; nt++) {
                    mma16816(acc[mt][nt], ah[mt], &bh[2 * nt]);
                    mma16816(acc[mt][nt], ah[mt], &blo[2 * nt]);
                    mma16816(acc[mt][nt], al[mt], &bh[2 * nt]);
                }
        }
        __syncthreads();

        if (kt + 2 < 32) load_stage((kt + 2) % 3, (kt + 2) * 32);
        CP_COMMIT();
    }

    #pragma unroll
    for (int nt = 0; nt < 4; nt++) {
        int n = n0 + wn * 32 + nt * 8 + t * 2;
        float b0 = bf[n], b1 = bf[n + 1];
        #pragma unroll
        for (int mt = 0; mt < 2; mt++) {
            int m = m0 + wm * 32 + mt * 16 + g;
            float2 v0 = make_float2(acc[mt][nt][0] + b0, acc[mt][nt][1] + b1);
            float2 v1 = make_float2(acc[mt][nt][2] + b0, acc[mt][nt][3] + b1);
            *reinterpret_cast<float2*>(C + (size_t)m * DD + n) = v0;
            *reinterpret_cast<float2*>(C + (size_t)(m + 8) * DD + n) = v1;
        }
    }
}

// ---------------------------------------------------------------------------
extern "C" void kernel_launch(void* const* d_in, const int* in_sizes, int n_in,
                              void* d_out, int out_size)
{
    const float* X    = (const float*)d_in[0];
    const int*   mask = (const int*)  d_in[1];
    const float* Wq   = (const float*)d_in[2];
    const float* bq   = (const float*)d_in[3];
    const float* Wk   = (const float*)d_in[4];
    const float* bk   = (const float*)d_in[5];
    const float* Wv   = (const float*)d_in[6];
    const float* bv   = (const float*)d_in[7];
    const float* Wf   = (const float*)d_in[8];
    const float* bf   = (const float*)d_in[9];
    float* out = (float*)d_out;

    cudaFuncSetAttribute(qkv_mma_kernel,
                         cudaFuncAttributeMaxDynamicSharedMemorySize, QKV_SMEM);
    cudaFuncSetAttribute(attn_mma_kernel,
                         cudaFuncAttributeMaxDynamicSharedMemorySize, ATTN_SMEM);
    cudaFuncSetAttribute(fuse_mma_kernel,
                         cudaFuncAttributeMaxDynamicSharedMemorySize, FUSE_SMEM);

    convW3_kernel<<<dim3(3, HH), 256>>>(Wq, Wk, Wv);

    dim3 grid1(TT / 128, BB * HH);
    qkv_mma_kernel<<<grid1, 256, QKV_SMEM>>>(X, bq, bk, bv);

    convW_kernel<<<dim3(32, 32), 256>>>(Wf);

    dim3 grid2(TT / 128, BB * HH);
    attn_mma_kernel<<<grid2, 256, ATTN_SMEM>>>(mask);

    dim3 grid4(DD / 64, (BB * TT) / 128);
    fuse_mma_kernel<<<grid4, 256, FUSE_SMEM>>>(bf, out);
}